// round 15
// baseline (speedup 1.0000x reference)
#include <cuda_runtime.h>
#include <cuda_bf16.h>
#include <math.h>

// Problem constants (fixed by the dataset)
#define NODES 100000
#define EDGES 1600000
#define GRAPHS 256
#define INF 128
#define HF 64
#define SCAN_BLK 256
#define NBLK ((NODES + SCAN_BLK - 1) / SCAN_BLK)   // 391

// ---------------- scratch (static device globals; no allocation) -------------
__device__ int   g_cnt_out[NODES];
__device__ int   g_cnt_in[NODES];
__device__ float g_ns[NODES];
__device__ float g_nd[NODES];
__device__ int   g_rowptr[NODES + 1];
__device__ int   g_cursor[NODES];
__device__ int2  g_csr[EDGES];                     // {src, w-bits}
__device__ int   g_blockSums[NBLK];
__device__ int   g_blockOff[NBLK];
__device__ __nv_bfloat162 g_tb[NODES * (HF / 2)];  // per-layer GEMM output (bf16x2)
__device__ __nv_bfloat162 g_aggb[NODES * (HF / 2)]; // layer-3 activated output (bf16x2)

// ---------------- init: zero degree counters ---------------------------------
__global__ void zero_counts_kernel() {
    int i = blockIdx.x * blockDim.x + threadIdx.x;
    if (i < NODES) { g_cnt_out[i] = 0; g_cnt_in[i] = 0; }
}

// ---------------- degree histogram -------------------------------------------
__global__ void degree_kernel(const int* __restrict__ src, const int* __restrict__ dst) {
    int e = blockIdx.x * blockDim.x + threadIdx.x;
    if (e < EDGES) {
        atomicAdd(&g_cnt_out[src[e]], 1);
        atomicAdd(&g_cnt_in[dst[e]], 1);
    }
}

// ---------------- norms (needs only degree counts) ----------------------------
__global__ void norm_kernel() {
    int i = blockIdx.x * blockDim.x + threadIdx.x;
    if (i < NODES) {
        g_ns[i] = rsqrtf(fmaxf((float)g_cnt_out[i], 1.0f));
        g_nd[i] = rsqrtf(fmaxf((float)g_cnt_in[i], 1.0f));
    }
}

// ---------------- 3-phase parallel scan of deg_in -----------------------------
__global__ void scan1_kernel() {
    int i = blockIdx.x * SCAN_BLK + threadIdx.x;
    int c = (i < NODES) ? g_cnt_in[i] : 0;
#pragma unroll
    for (int d = 16; d; d >>= 1) c += __shfl_down_sync(0xffffffffu, c, d);
    __shared__ int w[SCAN_BLK / 32];
    if ((threadIdx.x & 31) == 0) w[threadIdx.x >> 5] = c;
    __syncthreads();
    if (threadIdx.x < SCAN_BLK / 32) {
        int s = w[threadIdx.x];
#pragma unroll
        for (int d = SCAN_BLK / 64; d; d >>= 1) s += __shfl_down_sync(0xffu, s, d);
        if (threadIdx.x == 0) g_blockSums[blockIdx.x] = s;
    }
}

__global__ void scan2_kernel() {
    __shared__ int ss[512];
    int t = threadIdx.x;
    int v = (t < NBLK) ? g_blockSums[t] : 0;
    ss[t] = v;
    __syncthreads();
    for (int d = 1; d < 512; d <<= 1) {
        int o = (t >= d) ? ss[t - d] : 0;
        __syncthreads();
        ss[t] += o;
        __syncthreads();
    }
    if (t < NBLK) g_blockOff[t] = ss[t] - v;  // exclusive
}

__global__ void scan3_kernel() {
    int i = blockIdx.x * SCAN_BLK + threadIdx.x;
    int c = (i < NODES) ? g_cnt_in[i] : 0;
    int lane = threadIdx.x & 31, wid = threadIdx.x >> 5;
    int v = c;
#pragma unroll
    for (int d = 1; d < 32; d <<= 1) {
        int n = __shfl_up_sync(0xffffffffu, v, d);
        if (lane >= d) v += n;
    }
    __shared__ int wsum[SCAN_BLK / 32];
    if (lane == 31) wsum[wid] = v;
    __syncthreads();
    if (threadIdx.x < SCAN_BLK / 32) {
        int s = wsum[threadIdx.x];
#pragma unroll
        for (int d = 1; d < SCAN_BLK / 32; d <<= 1) {
            int n = __shfl_up_sync(0xffu, s, d);
            if ((int)threadIdx.x >= d) s += n;
        }
        wsum[threadIdx.x] = s;
    }
    __syncthreads();
    int excl = v - c + (wid > 0 ? wsum[wid - 1] : 0) + g_blockOff[blockIdx.x];
    if (i < NODES) {
        g_rowptr[i] = excl;
        g_cursor[i] = excl;
    }
    if (blockIdx.x == 0 && threadIdx.x == 0) g_rowptr[NODES] = EDGES;
}

// ---------------- CSR fill (by dst), packed int2 ------------------------------
__global__ void csr_fill_kernel(const int* __restrict__ src, const int* __restrict__ dst,
                                const float* __restrict__ ew) {
    int e = blockIdx.x * blockDim.x + threadIdx.x;
    if (e < EDGES) {
        int d = dst[e];
        int p = atomicAdd(&g_cursor[d], 1);
        g_csr[p] = make_int2(src[e], __float_as_int(ew[e]));
    }
}

// ---------------- layer-1 tf32 GEMM: tb = bf16( ns * (x @ W1) ) ---------------
#define ASTRIDE 132  // fp32 per A row: a-frag bank = 4*qr+qc (conflict-free)
#define BSTRIDE 72   // fp32 per W row: 72%32=8 -> b-frag bank = 8*qc+qr (conflict-free)
#define GEMM1_SMEM ((64 * ASTRIDE + 128 * BSTRIDE) * 4)  // 70656 B

__device__ __forceinline__ void mma_tf32(float* d, const unsigned* a, const unsigned* b) {
    asm volatile(
        "mma.sync.aligned.m16n8k8.row.col.f32.tf32.tf32.f32 "
        "{%0,%1,%2,%3}, {%4,%5,%6,%7}, {%8,%9}, {%0,%1,%2,%3};\n"
        : "+f"(d[0]), "+f"(d[1]), "+f"(d[2]), "+f"(d[3])
        : "r"(a[0]), "r"(a[1]), "r"(a[2]), "r"(a[3]), "r"(b[0]), "r"(b[1]));
}

__device__ __forceinline__ void cp_async16(void* smem_dst, const void* gmem_src, int srcBytes) {
    unsigned saddr = (unsigned)__cvta_generic_to_shared(smem_dst);
    asm volatile("cp.async.cg.shared.global [%0], [%1], 16, %2;"
                 :: "r"(saddr), "l"(gmem_src), "r"(srcBytes));
}

__global__ void __launch_bounds__(256) gemm1_kernel(const float* __restrict__ A,
                                                    const float* __restrict__ W,
                                                    __nv_bfloat162* __restrict__ outb) {
    extern __shared__ float smem_[];
    float* sA = smem_;                     // [64][ASTRIDE] raw fp32 bits
    float* sB = smem_ + 64 * ASTRIDE;      // [128][BSTRIDE] W as-is [k][n]

    const int tid = threadIdx.x;           // 0..255
    const int wid = tid >> 5;
    const int lane = tid & 31;
    const int qr = lane >> 2;
    const int qc = lane & 3;
    const int warp_m = wid & 3;            // 4 m-warps, 16 rows each
    const int warp_n = wid >> 2;           // 2 n-warps, 32 cols each
    const int row0 = blockIdx.x * 64;

    // ---- stage A tile: 64 rows x 128 floats = 2048 x 16B, 8 per thread ----
#pragma unroll
    for (int it = 0; it < 8; it++) {
        int idx = it * 256 + tid;
        int row = idx >> 5;                // 32 chunks per row
        int c = idx & 31;
        int grow = row0 + row;
        int ok = (grow < NODES) ? 16 : 0;
        int srow = (grow < NODES) ? grow : (NODES - 1);
        cp_async16(&sA[row * ASTRIDE + c * 4], &A[(long)srow * INF + c * 4], ok);
    }
    // ---- stage W: 128 rows x 64 floats = 2048 x 16B, 8 per thread ----
#pragma unroll
    for (int it = 0; it < 8; it++) {
        int idx = it * 256 + tid;
        int row = idx >> 4;                // 16 chunks per row
        int c = idx & 15;
        cp_async16(&sB[row * BSTRIDE + c * 4], &W[(long)row * HF + c * 4], 16);
    }
    asm volatile("cp.async.commit_group;");
    asm volatile("cp.async.wait_group 0;");
    __syncthreads();

    const unsigned* sAu = (const unsigned*)sA;
    const unsigned* sBu = (const unsigned*)sB;

    float acc[4][4];
#pragma unroll
    for (int ni = 0; ni < 4; ni++)
#pragma unroll
        for (int j = 0; j < 4; j++) acc[ni][j] = 0.0f;

#pragma unroll
    for (int kk8 = 0; kk8 < 16; kk8++) {
        const int kk = kk8 * 8;
        unsigned a[4], b[4][2];
        int r = warp_m * 16 + qr;
        a[0] = sAu[r * ASTRIDE + kk + qc];
        a[1] = sAu[(r + 8) * ASTRIDE + kk + qc];
        a[2] = sAu[r * ASTRIDE + kk + qc + 4];
        a[3] = sAu[(r + 8) * ASTRIDE + kk + qc + 4];
#pragma unroll
        for (int ni = 0; ni < 4; ni++) {
            int n = warp_n * 32 + ni * 8 + qr;
            b[ni][0] = sBu[(kk + qc) * BSTRIDE + n];
            b[ni][1] = sBu[(kk + qc + 4) * BSTRIDE + n];
        }
#pragma unroll
        for (int ni = 0; ni < 4; ni++)
            mma_tf32(acc[ni], a, b[ni]);
    }

    // ---- epilogue: row-scale by ns, pack to bf16x2 ----
    int r0 = row0 + warp_m * 16 + qr;
    int r1 = r0 + 8;
    float ns0 = (r0 < NODES) ? g_ns[r0] : 0.0f;
    float ns1 = (r1 < NODES) ? g_ns[r1] : 0.0f;
#pragma unroll
    for (int ni = 0; ni < 4; ni++) {
        int col2 = (warp_n * 32 + ni * 8 + qc * 2) >> 1;
        if (r0 < NODES)
            outb[(long)r0 * (HF / 2) + col2] =
                __floats2bfloat162_rn(acc[ni][0] * ns0, acc[ni][1] * ns0);
        if (r1 < NODES)
            outb[(long)r1 * (HF / 2) + col2] =
                __floats2bfloat162_rn(acc[ni][2] * ns1, acc[ni][3] * ns1);
    }
}

// ---------------- fused layer: agg(tb_in) -> transform -> bf16 GEMM -> tb_out -
// Phase A: QUARTER-warp per node (8 lanes x 16B uint4 cover the 128B line);
//          warp serves 4 nodes concurrently, 2 rounds -> 16 lines in flight/warp.
// Phase B: 64x64 GEMM via mma.m16n8k16 bf16.
#define BPAD 72  // bf16 elems per row; 144B stride -> conflict-free frag loads

__device__ __forceinline__ void mma_bf16(float* d, const unsigned* a, const unsigned* b) {
    asm volatile(
        "mma.sync.aligned.m16n8k16.row.col.f32.bf16.bf16.f32 "
        "{%0,%1,%2,%3}, {%4,%5,%6,%7}, {%8,%9}, {%0,%1,%2,%3};\n"
        : "+f"(d[0]), "+f"(d[1]), "+f"(d[2]), "+f"(d[3])
        : "r"(a[0]), "r"(a[1]), "r"(a[2]), "r"(a[3]), "r"(b[0]), "r"(b[1]));
}

// accumulate one edge: v = uint4 of 8 bf16 features, w = edge weight
#define ACC_EDGE8(e, v)                                                       \
    {                                                                         \
        float w = __int_as_float((e).y);                                      \
        float2 f0 = __bfloat1622float2(*(__nv_bfloat162*)&(v).x);             \
        float2 f1 = __bfloat1622float2(*(__nv_bfloat162*)&(v).y);             \
        float2 f2 = __bfloat1622float2(*(__nv_bfloat162*)&(v).z);             \
        float2 f3 = __bfloat1622float2(*(__nv_bfloat162*)&(v).w);             \
        a0 = fmaf(f0.x, w, a0); a1 = fmaf(f0.y, w, a1);                       \
        a2 = fmaf(f1.x, w, a2); a3 = fmaf(f1.y, w, a3);                       \
        a4 = fmaf(f2.x, w, a4); a5 = fmaf(f2.y, w, a5);                       \
        a6 = fmaf(f3.x, w, a6); a7 = fmaf(f3.y, w, a7);                       \
    }

__global__ void fused_layer_kernel(const __nv_bfloat162* __restrict__ tb_in,
                                   const float* __restrict__ W,
                                   const float* __restrict__ bprev,
                                   __nv_bfloat162* __restrict__ tb_out) {
    __shared__ __nv_bfloat16 sA[64 * BPAD];  // [row][k]
    __shared__ __nv_bfloat16 sW[64 * BPAD];  // [n][k] (W transposed)

    const int tid = threadIdx.x;     // 0..255
    const int wid = tid >> 5;        // 0..7
    const int lane = tid & 31;
    const int row0 = blockIdx.x * 64;
    const uint4* tbu = (const uint4*)tb_in;  // [node][8] x 16B (8 bf16 each)

    // load W transposed -> sW[n][k]
#pragma unroll
    for (int it = 0; it < 16; it++) {
        int idx = it * 256 + tid;    // 4096
        int k = idx >> 6;
        int n = idx & 63;
        sW[n * BPAD + k] = __float2bfloat16(W[k * HF + n]);
    }

    // Phase A: quarter-warp per node, 2 rounds of 4 concurrent nodes per warp
    const int q = lane >> 3;         // quarter id 0..3
    const int ql = lane & 7;         // 0..7 -> features 8*ql..8*ql+7
    const float4 bb0 = ((const float4*)bprev)[2 * ql];
    const float4 bb1 = ((const float4*)bprev)[2 * ql + 1];
#pragma unroll 1
    for (int rp = 0; rp < 2; rp++) {
        int lrow = wid * 8 + rp * 4 + q;
        int row = row0 + lrow;
        float a0 = 0.f, a1 = 0.f, a2 = 0.f, a3 = 0.f;
        float a4 = 0.f, a5 = 0.f, a6 = 0.f, a7 = 0.f;
        int j = 0, end = 0;
        if (row < NODES) { j = g_rowptr[row]; end = g_rowptr[row + 1]; }
        for (; j + 3 < end; j += 4) {
            int2 e0 = g_csr[j], e1 = g_csr[j + 1], e2 = g_csr[j + 2], e3 = g_csr[j + 3];
            uint4 v0 = tbu[(long)e0.x * 8 + ql];
            uint4 v1 = tbu[(long)e1.x * 8 + ql];
            uint4 v2 = tbu[(long)e2.x * 8 + ql];
            uint4 v3 = tbu[(long)e3.x * 8 + ql];
            ACC_EDGE8(e0, v0) ACC_EDGE8(e1, v1) ACC_EDGE8(e2, v2) ACC_EDGE8(e3, v3)
        }
        for (; j < end; j++) {
            int2 e0 = g_csr[j];
            uint4 v0 = tbu[(long)e0.x * 8 + ql];
            ACC_EDGE8(e0, v0)
        }
        if (row < NODES) {
            float nd = g_nd[row];
            float ns = g_ns[row];
            a0 = fmaxf(fmaf(a0, nd, bb0.x), 0.0f) * ns;
            a1 = fmaxf(fmaf(a1, nd, bb0.y), 0.0f) * ns;
            a2 = fmaxf(fmaf(a2, nd, bb0.z), 0.0f) * ns;
            a3 = fmaxf(fmaf(a3, nd, bb0.w), 0.0f) * ns;
            a4 = fmaxf(fmaf(a4, nd, bb1.x), 0.0f) * ns;
            a5 = fmaxf(fmaf(a5, nd, bb1.y), 0.0f) * ns;
            a6 = fmaxf(fmaf(a6, nd, bb1.z), 0.0f) * ns;
            a7 = fmaxf(fmaf(a7, nd, bb1.w), 0.0f) * ns;
        }
        __nv_bfloat162 p0 = __floats2bfloat162_rn(a0, a1);
        __nv_bfloat162 p1 = __floats2bfloat162_rn(a2, a3);
        __nv_bfloat162 p2 = __floats2bfloat162_rn(a4, a5);
        __nv_bfloat162 p3 = __floats2bfloat162_rn(a6, a7);
        uint4 pk;
        pk.x = *(unsigned*)&p0;
        pk.y = *(unsigned*)&p1;
        pk.z = *(unsigned*)&p2;
        pk.w = *(unsigned*)&p3;
        *(uint4*)&sA[lrow * BPAD + 8 * ql] = pk;
    }
    __syncthreads();

    // Phase B: GEMM sA @ sW^T
    const int warp_m = wid & 3;
    const int warp_n = wid >> 2;
    const int qr = lane >> 2;
    const int qc = lane & 3;

    float acc[4][4];
#pragma unroll
    for (int ni = 0; ni < 4; ni++)
#pragma unroll
        for (int j = 0; j < 4; j++) acc[ni][j] = 0.0f;

#pragma unroll
    for (int ks = 0; ks < 4; ks++) {
        const int kk = ks * 16;
        unsigned a[4], b[4][2];
        int ra = warp_m * 16 + qr;
        a[0] = *(const unsigned*)&sA[ra * BPAD + kk + 2 * qc];
        a[1] = *(const unsigned*)&sA[(ra + 8) * BPAD + kk + 2 * qc];
        a[2] = *(const unsigned*)&sA[ra * BPAD + kk + 2 * qc + 8];
        a[3] = *(const unsigned*)&sA[(ra + 8) * BPAD + kk + 2 * qc + 8];
#pragma unroll
        for (int ni = 0; ni < 4; ni++) {
            int n = warp_n * 32 + ni * 8 + qr;
            b[ni][0] = *(const unsigned*)&sW[n * BPAD + kk + 2 * qc];
            b[ni][1] = *(const unsigned*)&sW[n * BPAD + kk + 2 * qc + 8];
        }
#pragma unroll
        for (int ni = 0; ni < 4; ni++)
            mma_bf16(acc[ni], a, b[ni]);
    }

    // epilogue
    int r0 = row0 + warp_m * 16 + qr;
    int r1 = r0 + 8;
#pragma unroll
    for (int ni = 0; ni < 4; ni++) {
        int col2 = (warp_n * 32 + ni * 8 + qc * 2) >> 1;
        if (r0 < NODES)
            tb_out[(long)r0 * (HF / 2) + col2] = __floats2bfloat162_rn(acc[ni][0], acc[ni][1]);
        if (r1 < NODES)
            tb_out[(long)r1 * (HF / 2) + col2] = __floats2bfloat162_rn(acc[ni][2], acc[ni][3]);
    }
}

// ---------------- layer-3 agg + activate -> bf16: aggb = bf16(relu(agg*nd+b3))
// quarter-warp per node; block of 256 covers 32 nodes.
__global__ void agg3_kernel(const __nv_bfloat162* __restrict__ tb,
                            const float* __restrict__ b3,
                            __nv_bfloat162* __restrict__ outb) {
    int node = blockIdx.x * 32 + (threadIdx.x >> 3);
    if (node >= NODES) return;
    int ql = threadIdx.x & 7;
    const uint4* tbu = (const uint4*)tb;
    const float4 bb0 = ((const float4*)b3)[2 * ql];
    const float4 bb1 = ((const float4*)b3)[2 * ql + 1];
    int j = g_rowptr[node];
    int end = g_rowptr[node + 1];
    float a0 = 0.f, a1 = 0.f, a2 = 0.f, a3 = 0.f;
    float a4 = 0.f, a5 = 0.f, a6 = 0.f, a7 = 0.f;
    for (; j + 3 < end; j += 4) {
        int2 e0 = g_csr[j], e1 = g_csr[j + 1], e2 = g_csr[j + 2], e3 = g_csr[j + 3];
        uint4 v0 = tbu[(long)e0.x * 8 + ql];
        uint4 v1 = tbu[(long)e1.x * 8 + ql];
        uint4 v2 = tbu[(long)e2.x * 8 + ql];
        uint4 v3 = tbu[(long)e3.x * 8 + ql];
        ACC_EDGE8(e0, v0) ACC_EDGE8(e1, v1) ACC_EDGE8(e2, v2) ACC_EDGE8(e3, v3)
    }
    for (; j < end; j++) {
        int2 e0 = g_csr[j];
        uint4 v0 = tbu[(long)e0.x * 8 + ql];
        ACC_EDGE8(e0, v0)
    }
    float nd = g_nd[node];
    a0 = fmaxf(fmaf(a0, nd, bb0.x), 0.0f);
    a1 = fmaxf(fmaf(a1, nd, bb0.y), 0.0f);
    a2 = fmaxf(fmaf(a2, nd, bb0.z), 0.0f);
    a3 = fmaxf(fmaf(a3, nd, bb0.w), 0.0f);
    a4 = fmaxf(fmaf(a4, nd, bb1.x), 0.0f);
    a5 = fmaxf(fmaf(a5, nd, bb1.y), 0.0f);
    a6 = fmaxf(fmaf(a6, nd, bb1.z), 0.0f);
    a7 = fmaxf(fmaf(a7, nd, bb1.w), 0.0f);
    __nv_bfloat162 p0 = __floats2bfloat162_rn(a0, a1);
    __nv_bfloat162 p1 = __floats2bfloat162_rn(a2, a3);
    __nv_bfloat162 p2 = __floats2bfloat162_rn(a4, a5);
    __nv_bfloat162 p3 = __floats2bfloat162_rn(a6, a7);
    uint4 pk;
    pk.x = *(unsigned*)&p0;
    pk.y = *(unsigned*)&p1;
    pk.z = *(unsigned*)&p2;
    pk.w = *(unsigned*)&p3;
    *(uint4*)&outb[(long)node * (HF / 2) + 4 * ql] = pk;
}

// ---------------- pool (mean per graph) + MLP head + sigmoid ------------------
__device__ __forceinline__ int lower_bound_dev(const int* __restrict__ a, int n, int key) {
    int lo = 0, hi = n;
    while (lo < hi) {
        int mid = (lo + hi) >> 1;
        if (a[mid] < key) lo = mid + 1; else hi = mid;
    }
    return lo;
}

__global__ void pool_mlp_kernel(const __nv_bfloat162* __restrict__ aggb,
                                const int* __restrict__ gid,
                                const float* __restrict__ Dw1, const float* __restrict__ Db1,
                                const float* __restrict__ Dw2, const float* __restrict__ Db2,
                                const float* __restrict__ Dw3, const float* __restrict__ Db3,
                                float* __restrict__ out) {
    int g = blockIdx.x;
    int t = threadIdx.x;  // 32 threads: t covers bf16x2 slot (2 features)
    int start = lower_bound_dev(gid, NODES, g);
    int end = lower_bound_dev(gid, NODES, g + 1);

    float s0 = 0.0f, s1 = 0.0f;
    for (int n = start; n < end; n++) {
        float2 v = __bfloat1622float2(aggb[(long)n * (HF / 2) + t]);
        s0 += v.x;
        s1 += v.y;
    }
    float cnt = fmaxf((float)(end - start), 1.0f);

    __shared__ float pooled[64];
    __shared__ float h1[16];
    __shared__ float h2[8];
    pooled[2 * t] = s0 / cnt;
    pooled[2 * t + 1] = s1 / cnt;
    __syncthreads();

    if (t < 16) {
        float s = Db1[t];
#pragma unroll
        for (int k = 0; k < 64; k++) s = fmaf(pooled[k], Dw1[k * 16 + t], s);
        h1[t] = fmaxf(s, 0.0f);
    }
    __syncthreads();
    if (t < 8) {
        float s = Db2[t];
#pragma unroll
        for (int k = 0; k < 16; k++) s = fmaf(h1[k], Dw2[k * 8 + t], s);
        h2[t] = fmaxf(s, 0.0f);
    }
    __syncthreads();
    if (t == 0) {
        float s = Db3[0];
#pragma unroll
        for (int k = 0; k < 8; k++) s = fmaf(h2[k], Dw3[k], s);
        out[g] = 1.0f / (1.0f + expf(-s));
    }
}

// ---------------- launch ------------------------------------------------------
extern "C" void kernel_launch(void* const* d_in, const int* in_sizes, int n_in,
                              void* d_out, int out_size) {
    const float* x   = (const float*)d_in[0];
    const int*   src = (const int*)d_in[1];
    const int*   dst = (const int*)d_in[2];
    const float* ew  = (const float*)d_in[3];
    const int*   gid = (const int*)d_in[4];
    const float* W1  = (const float*)d_in[5];
    const float* b1  = (const float*)d_in[6];
    const float* W2  = (const float*)d_in[7];
    const float* b2  = (const float*)d_in[8];
    const float* W3  = (const float*)d_in[9];
    const float* b3  = (const float*)d_in[10];
    const float* Dw1 = (const float*)d_in[11];
    const float* Db1 = (const float*)d_in[12];
    const float* Dw2 = (const float*)d_in[13];
    const float* Db2 = (const float*)d_in[14];
    const float* Dw3 = (const float*)d_in[15];
    const float* Db3 = (const float*)d_in[16];
    float* out = (float*)d_out;

    __nv_bfloat162* tb_ptr;  cudaGetSymbolAddress((void**)&tb_ptr, g_tb);
    __nv_bfloat162* agg_ptr; cudaGetSymbolAddress((void**)&agg_ptr, g_aggb);

    const int NB = (NODES + 255) / 256;
    const int EB = (EDGES + 255) / 256;
    const int GB = (NODES + 63) / 64;    // 64-row tiles
    const int A3B = (NODES + 31) / 32;   // agg3 blocks (32 nodes each)

    // One-time setup: side stream + events + gemm1 dynamic smem opt-in.
    static cudaStream_t s2 = nullptr;
    static cudaEvent_t evA = nullptr, evB = nullptr;
    static bool inited = false;
    if (!inited) {
        cudaFuncSetAttribute(gemm1_kernel, cudaFuncAttributeMaxDynamicSharedMemorySize,
                             GEMM1_SMEM);
        if (cudaStreamCreateWithFlags(&s2, cudaStreamNonBlocking) != cudaSuccess) s2 = nullptr;
        if (s2) {
            if (cudaEventCreateWithFlags(&evA, cudaEventDisableTiming) != cudaSuccess ||
                cudaEventCreateWithFlags(&evB, cudaEventDisableTiming) != cudaSuccess) {
                s2 = nullptr;
            }
        }
        inited = true;
    }

    // 1-2: degree histogram (common dependency)
    zero_counts_kernel<<<NB, 256>>>();
    degree_kernel<<<EB, 256>>>(src, dst);

    if (s2) {
        // fork: CSR build on s2, norms+gemm1 on main — independent given degrees
        cudaEventRecord(evA, 0);
        cudaStreamWaitEvent(s2, evA, 0);

        norm_kernel<<<NB, 256>>>();
        gemm1_kernel<<<GB, 256, GEMM1_SMEM>>>(x, W1, tb_ptr);

        scan1_kernel<<<NBLK, SCAN_BLK, 0, s2>>>();
        scan2_kernel<<<1, 512, 0, s2>>>();
        scan3_kernel<<<NBLK, SCAN_BLK, 0, s2>>>();
        csr_fill_kernel<<<EB, 256, 0, s2>>>(src, dst, ew);
        cudaEventRecord(evB, s2);
        cudaStreamWaitEvent(0, evB, 0);
    } else {
        // sequential fallback
        norm_kernel<<<NB, 256>>>();
        gemm1_kernel<<<GB, 256, GEMM1_SMEM>>>(x, W1, tb_ptr);
        scan1_kernel<<<NBLK, SCAN_BLK>>>();
        scan2_kernel<<<1, 512>>>();
        scan3_kernel<<<NBLK, SCAN_BLK>>>();
        csr_fill_kernel<<<EB, 256>>>(src, dst, ew);
    }

    // fused agg+transform+GEMM for layers 2 and 3
    fused_layer_kernel<<<GB, 256>>>(tb_ptr, W2, b1, tb_ptr);
    fused_layer_kernel<<<GB, 256>>>(tb_ptr, W3, b2, tb_ptr);

    // layer-3 aggregation + activation (bf16 out)
    agg3_kernel<<<A3B, 256>>>(tb_ptr, b3, agg_ptr);

    // pool + MLP + sigmoid
    pool_mlp_kernel<<<GRAPHS, 32>>>(agg_ptr, gid, Dw1, Db1, Dw2, Db2, Dw3, Db3, out);
}

// round 16
// speedup vs baseline: 1.3897x; 1.3897x over previous
#include <cuda_runtime.h>
#include <cuda_bf16.h>
#include <math.h>

// Problem constants (fixed by the dataset)
#define NODES 100000
#define EDGES 1600000
#define GRAPHS 256
#define INF 128
#define HF 64
#define SCAN_BLK 256
#define NBLK ((NODES + SCAN_BLK - 1) / SCAN_BLK)   // 391

// ---------------- scratch (static device globals; no allocation) -------------
__device__ int   g_cnt_out[NODES];
__device__ int   g_cnt_in[NODES];
__device__ float g_ns[NODES];
__device__ float g_nd[NODES];
__device__ int   g_rowptr[NODES + 1];
__device__ int   g_cursor[NODES];
__device__ int2  g_csr[EDGES];                     // {src, w-bits}
__device__ int   g_blockSums[NBLK];
__device__ int   g_blockOff[NBLK];
__device__ __nv_bfloat162 g_tb[NODES * (HF / 2)];  // per-layer GEMM output (bf16x2)
__device__ __nv_bfloat162 g_aggb[NODES * (HF / 2)]; // layer-3 activated output (bf16x2)

// ---------------- init: zero degree counters ---------------------------------
__global__ void zero_counts_kernel() {
    int i = blockIdx.x * blockDim.x + threadIdx.x;
    if (i < NODES) { g_cnt_out[i] = 0; g_cnt_in[i] = 0; }
}

// ---------------- degree histogram -------------------------------------------
__global__ void degree_kernel(const int* __restrict__ src, const int* __restrict__ dst) {
    int e = blockIdx.x * blockDim.x + threadIdx.x;
    if (e < EDGES) {
        atomicAdd(&g_cnt_out[src[e]], 1);
        atomicAdd(&g_cnt_in[dst[e]], 1);
    }
}

// ---------------- norms (needs only degree counts) ----------------------------
__global__ void norm_kernel() {
    int i = blockIdx.x * blockDim.x + threadIdx.x;
    if (i < NODES) {
        g_ns[i] = rsqrtf(fmaxf((float)g_cnt_out[i], 1.0f));
        g_nd[i] = rsqrtf(fmaxf((float)g_cnt_in[i], 1.0f));
    }
}

// ---------------- 3-phase parallel scan of deg_in -----------------------------
__global__ void scan1_kernel() {
    int i = blockIdx.x * SCAN_BLK + threadIdx.x;
    int c = (i < NODES) ? g_cnt_in[i] : 0;
#pragma unroll
    for (int d = 16; d; d >>= 1) c += __shfl_down_sync(0xffffffffu, c, d);
    __shared__ int w[SCAN_BLK / 32];
    if ((threadIdx.x & 31) == 0) w[threadIdx.x >> 5] = c;
    __syncthreads();
    if (threadIdx.x < SCAN_BLK / 32) {
        int s = w[threadIdx.x];
#pragma unroll
        for (int d = SCAN_BLK / 64; d; d >>= 1) s += __shfl_down_sync(0xffu, s, d);
        if (threadIdx.x == 0) g_blockSums[blockIdx.x] = s;
    }
}

__global__ void scan2_kernel() {
    __shared__ int ss[512];
    int t = threadIdx.x;
    int v = (t < NBLK) ? g_blockSums[t] : 0;
    ss[t] = v;
    __syncthreads();
    for (int d = 1; d < 512; d <<= 1) {
        int o = (t >= d) ? ss[t - d] : 0;
        __syncthreads();
        ss[t] += o;
        __syncthreads();
    }
    if (t < NBLK) g_blockOff[t] = ss[t] - v;  // exclusive
}

__global__ void scan3_kernel() {
    int i = blockIdx.x * SCAN_BLK + threadIdx.x;
    int c = (i < NODES) ? g_cnt_in[i] : 0;
    int lane = threadIdx.x & 31, wid = threadIdx.x >> 5;
    int v = c;
#pragma unroll
    for (int d = 1; d < 32; d <<= 1) {
        int n = __shfl_up_sync(0xffffffffu, v, d);
        if (lane >= d) v += n;
    }
    __shared__ int wsum[SCAN_BLK / 32];
    if (lane == 31) wsum[wid] = v;
    __syncthreads();
    if (threadIdx.x < SCAN_BLK / 32) {
        int s = wsum[threadIdx.x];
#pragma unroll
        for (int d = 1; d < SCAN_BLK / 32; d <<= 1) {
            int n = __shfl_up_sync(0xffu, s, d);
            if ((int)threadIdx.x >= d) s += n;
        }
        wsum[threadIdx.x] = s;
    }
    __syncthreads();
    int excl = v - c + (wid > 0 ? wsum[wid - 1] : 0) + g_blockOff[blockIdx.x];
    if (i < NODES) {
        g_rowptr[i] = excl;
        g_cursor[i] = excl;
    }
    if (blockIdx.x == 0 && threadIdx.x == 0) g_rowptr[NODES] = EDGES;
}

// ---------------- CSR fill (by dst), packed int2 ------------------------------
__global__ void csr_fill_kernel(const int* __restrict__ src, const int* __restrict__ dst,
                                const float* __restrict__ ew) {
    int e = blockIdx.x * blockDim.x + threadIdx.x;
    if (e < EDGES) {
        int d = dst[e];
        int p = atomicAdd(&g_cursor[d], 1);
        g_csr[p] = make_int2(src[e], __float_as_int(ew[e]));
    }
}

// ---------------- layer-1 tf32 GEMM: tb = bf16( ns * (x @ W1) ) ---------------
#define ASTRIDE 132  // fp32 per A row: a-frag bank = 4*qr+qc (conflict-free)
#define BSTRIDE 72   // fp32 per W row: 72%32=8 -> b-frag bank = 8*qc+qr (conflict-free)
#define GEMM1_SMEM ((64 * ASTRIDE + 128 * BSTRIDE) * 4)  // 70656 B

__device__ __forceinline__ void mma_tf32(float* d, const unsigned* a, const unsigned* b) {
    asm volatile(
        "mma.sync.aligned.m16n8k8.row.col.f32.tf32.tf32.f32 "
        "{%0,%1,%2,%3}, {%4,%5,%6,%7}, {%8,%9}, {%0,%1,%2,%3};\n"
        : "+f"(d[0]), "+f"(d[1]), "+f"(d[2]), "+f"(d[3])
        : "r"(a[0]), "r"(a[1]), "r"(a[2]), "r"(a[3]), "r"(b[0]), "r"(b[1]));
}

__device__ __forceinline__ void cp_async16(void* smem_dst, const void* gmem_src, int srcBytes) {
    unsigned saddr = (unsigned)__cvta_generic_to_shared(smem_dst);
    asm volatile("cp.async.cg.shared.global [%0], [%1], 16, %2;"
                 :: "r"(saddr), "l"(gmem_src), "r"(srcBytes));
}

__global__ void __launch_bounds__(256) gemm1_kernel(const float* __restrict__ A,
                                                    const float* __restrict__ W,
                                                    __nv_bfloat162* __restrict__ outb) {
    extern __shared__ float smem_[];
    float* sA = smem_;                     // [64][ASTRIDE] raw fp32 bits
    float* sB = smem_ + 64 * ASTRIDE;      // [128][BSTRIDE] W as-is [k][n]

    const int tid = threadIdx.x;           // 0..255
    const int wid = tid >> 5;
    const int lane = tid & 31;
    const int qr = lane >> 2;
    const int qc = lane & 3;
    const int warp_m = wid & 3;            // 4 m-warps, 16 rows each
    const int warp_n = wid >> 2;           // 2 n-warps, 32 cols each
    const int row0 = blockIdx.x * 64;

    // ---- stage A tile: 64 rows x 128 floats = 2048 x 16B, 8 per thread ----
#pragma unroll
    for (int it = 0; it < 8; it++) {
        int idx = it * 256 + tid;
        int row = idx >> 5;                // 32 chunks per row
        int c = idx & 31;
        int grow = row0 + row;
        int ok = (grow < NODES) ? 16 : 0;
        int srow = (grow < NODES) ? grow : (NODES - 1);
        cp_async16(&sA[row * ASTRIDE + c * 4], &A[(long)srow * INF + c * 4], ok);
    }
    // ---- stage W: 128 rows x 64 floats = 2048 x 16B, 8 per thread ----
#pragma unroll
    for (int it = 0; it < 8; it++) {
        int idx = it * 256 + tid;
        int row = idx >> 4;                // 16 chunks per row
        int c = idx & 15;
        cp_async16(&sB[row * BSTRIDE + c * 4], &W[(long)row * HF + c * 4], 16);
    }
    asm volatile("cp.async.commit_group;");
    asm volatile("cp.async.wait_group 0;");
    __syncthreads();

    const unsigned* sAu = (const unsigned*)sA;
    const unsigned* sBu = (const unsigned*)sB;

    float acc[4][4];
#pragma unroll
    for (int ni = 0; ni < 4; ni++)
#pragma unroll
        for (int j = 0; j < 4; j++) acc[ni][j] = 0.0f;

#pragma unroll
    for (int kk8 = 0; kk8 < 16; kk8++) {
        const int kk = kk8 * 8;
        unsigned a[4], b[4][2];
        int r = warp_m * 16 + qr;
        a[0] = sAu[r * ASTRIDE + kk + qc];
        a[1] = sAu[(r + 8) * ASTRIDE + kk + qc];
        a[2] = sAu[r * ASTRIDE + kk + qc + 4];
        a[3] = sAu[(r + 8) * ASTRIDE + kk + qc + 4];
#pragma unroll
        for (int ni = 0; ni < 4; ni++) {
            int n = warp_n * 32 + ni * 8 + qr;
            b[ni][0] = sBu[(kk + qc) * BSTRIDE + n];
            b[ni][1] = sBu[(kk + qc + 4) * BSTRIDE + n];
        }
#pragma unroll
        for (int ni = 0; ni < 4; ni++)
            mma_tf32(acc[ni], a, b[ni]);
    }

    // ---- epilogue: row-scale by ns, pack to bf16x2 ----
    int r0 = row0 + warp_m * 16 + qr;
    int r1 = r0 + 8;
    float ns0 = (r0 < NODES) ? g_ns[r0] : 0.0f;
    float ns1 = (r1 < NODES) ? g_ns[r1] : 0.0f;
#pragma unroll
    for (int ni = 0; ni < 4; ni++) {
        int col2 = (warp_n * 32 + ni * 8 + qc * 2) >> 1;
        if (r0 < NODES)
            outb[(long)r0 * (HF / 2) + col2] =
                __floats2bfloat162_rn(acc[ni][0] * ns0, acc[ni][1] * ns0);
        if (r1 < NODES)
            outb[(long)r1 * (HF / 2) + col2] =
                __floats2bfloat162_rn(acc[ni][2] * ns1, acc[ni][3] * ns1);
    }
}

// ---------------- fused layer: agg(tb_in) -> transform -> bf16 GEMM -> tb_out -
// Phase A: half-warp per node, 4-edge unroll; DYNAMIC row assignment via a
//          shared-memory counter so blocks self-balance (no warp straggler).
// Phase B: 64x64 GEMM via mma.m16n8k16 bf16.
#define BPAD 72  // bf16 elems per row; 144B stride -> conflict-free frag loads

__device__ __forceinline__ void mma_bf16(float* d, const unsigned* a, const unsigned* b) {
    asm volatile(
        "mma.sync.aligned.m16n8k16.row.col.f32.bf16.bf16.f32 "
        "{%0,%1,%2,%3}, {%4,%5,%6,%7}, {%8,%9}, {%0,%1,%2,%3};\n"
        : "+f"(d[0]), "+f"(d[1]), "+f"(d[2]), "+f"(d[3])
        : "r"(a[0]), "r"(a[1]), "r"(a[2]), "r"(a[3]), "r"(b[0]), "r"(b[1]));
}

#define ACC_EDGE(e, v)                                                        \
    {                                                                         \
        float w = __int_as_float((e).y);                                      \
        float2 lo = __bfloat1622float2(*(__nv_bfloat162*)&(v).x);             \
        float2 hi = __bfloat1622float2(*(__nv_bfloat162*)&(v).y);             \
        a0 = fmaf(lo.x, w, a0); a1 = fmaf(lo.y, w, a1);                       \
        a2 = fmaf(hi.x, w, a2); a3 = fmaf(hi.y, w, a3);                       \
    }

__global__ void fused_layer_kernel(const __nv_bfloat162* __restrict__ tb_in,
                                   const float* __restrict__ W,
                                   const float* __restrict__ bprev,
                                   __nv_bfloat162* __restrict__ tb_out) {
    __shared__ __nv_bfloat16 sA[64 * BPAD];  // [row][k]
    __shared__ __nv_bfloat16 sW[64 * BPAD];  // [n][k] (W transposed)
    __shared__ int s_next;                   // dynamic row cursor (0..63)

    const int tid = threadIdx.x;     // 0..255
    const int wid = tid >> 5;        // 0..7
    const int lane = tid & 31;
    const int row0 = blockIdx.x * 64;
    const uint2* tbu = (const uint2*)tb_in;  // [node][16] x 8B (4 bf16 each)

    if (tid == 0) s_next = 0;

    // load W transposed -> sW[n][k]
#pragma unroll
    for (int it = 0; it < 16; it++) {
        int idx = it * 256 + tid;    // 4096
        int k = idx >> 6;
        int n = idx & 63;
        sW[n * BPAD + k] = __float2bfloat16(W[k * HF + n]);
    }
    __syncthreads();                 // s_next visible before pops

    // Phase A: half-warp per node, rows popped dynamically
    const int hl = lane & 15;        // 0..15 -> features 4*hl..4*hl+3
    const int hsrc = lane & 16;      // shuffle source lane (0 or 16)
    const unsigned hmask = (lane < 16) ? 0x0000FFFFu : 0xFFFF0000u;
    const float4 bb = ((const float4*)bprev)[hl];
    while (true) {
        int lrow = 0;
        if (hl == 0) lrow = atomicAdd(&s_next, 1);
        lrow = __shfl_sync(hmask, lrow, hsrc);
        if (lrow >= 64) break;
        int row = row0 + lrow;
        float a0 = 0.f, a1 = 0.f, a2 = 0.f, a3 = 0.f;
        int j = 0, end = 0;
        if (row < NODES) { j = g_rowptr[row]; end = g_rowptr[row + 1]; }
        for (; j + 3 < end; j += 4) {
            int2 e0 = g_csr[j], e1 = g_csr[j + 1], e2 = g_csr[j + 2], e3 = g_csr[j + 3];
            uint2 v0 = tbu[(long)e0.x * 16 + hl];
            uint2 v1 = tbu[(long)e1.x * 16 + hl];
            uint2 v2 = tbu[(long)e2.x * 16 + hl];
            uint2 v3 = tbu[(long)e3.x * 16 + hl];
            ACC_EDGE(e0, v0) ACC_EDGE(e1, v1) ACC_EDGE(e2, v2) ACC_EDGE(e3, v3)
        }
        for (; j < end; j++) {
            int2 e0 = g_csr[j];
            uint2 v0 = tbu[(long)e0.x * 16 + hl];
            ACC_EDGE(e0, v0)
        }
        if (row < NODES) {
            float nd = g_nd[row];
            float ns = g_ns[row];
            a0 = fmaxf(fmaf(a0, nd, bb.x), 0.0f) * ns;
            a1 = fmaxf(fmaf(a1, nd, bb.y), 0.0f) * ns;
            a2 = fmaxf(fmaf(a2, nd, bb.z), 0.0f) * ns;
            a3 = fmaxf(fmaf(a3, nd, bb.w), 0.0f) * ns;
        }
        __nv_bfloat162 p0 = __floats2bfloat162_rn(a0, a1);
        __nv_bfloat162 p1 = __floats2bfloat162_rn(a2, a3);
        uint2 pk;
        pk.x = *(unsigned*)&p0;
        pk.y = *(unsigned*)&p1;
        *(uint2*)&sA[lrow * BPAD + 4 * hl] = pk;
    }
    __syncthreads();

    // Phase B: GEMM sA @ sW^T
    const int warp_m = wid & 3;
    const int warp_n = wid >> 2;
    const int qr = lane >> 2;
    const int qc = lane & 3;

    float acc[4][4];
#pragma unroll
    for (int ni = 0; ni < 4; ni++)
#pragma unroll
        for (int j = 0; j < 4; j++) acc[ni][j] = 0.0f;

#pragma unroll
    for (int ks = 0; ks < 4; ks++) {
        const int kk = ks * 16;
        unsigned a[4], b[4][2];
        int ra = warp_m * 16 + qr;
        a[0] = *(const unsigned*)&sA[ra * BPAD + kk + 2 * qc];
        a[1] = *(const unsigned*)&sA[(ra + 8) * BPAD + kk + 2 * qc];
        a[2] = *(const unsigned*)&sA[ra * BPAD + kk + 2 * qc + 8];
        a[3] = *(const unsigned*)&sA[(ra + 8) * BPAD + kk + 2 * qc + 8];
#pragma unroll
        for (int ni = 0; ni < 4; ni++) {
            int n = warp_n * 32 + ni * 8 + qr;
            b[ni][0] = *(const unsigned*)&sW[n * BPAD + kk + 2 * qc];
            b[ni][1] = *(const unsigned*)&sW[n * BPAD + kk + 2 * qc + 8];
        }
#pragma unroll
        for (int ni = 0; ni < 4; ni++)
            mma_bf16(acc[ni], a, b[ni]);
    }

    // epilogue
    int r0 = row0 + warp_m * 16 + qr;
    int r1 = r0 + 8;
#pragma unroll
    for (int ni = 0; ni < 4; ni++) {
        int col2 = (warp_n * 32 + ni * 8 + qc * 2) >> 1;
        if (r0 < NODES)
            tb_out[(long)r0 * (HF / 2) + col2] = __floats2bfloat162_rn(acc[ni][0], acc[ni][1]);
        if (r1 < NODES)
            tb_out[(long)r1 * (HF / 2) + col2] = __floats2bfloat162_rn(acc[ni][2], acc[ni][3]);
    }
}

// ---------------- layer-3 agg + activate -> bf16: aggb = bf16(relu(agg*nd+b3))
// half-warp per node, 4-edge unroll; block of 256 covers 16 nodes.
__global__ void agg3_kernel(const __nv_bfloat162* __restrict__ tb,
                            const float* __restrict__ b3,
                            __nv_bfloat162* __restrict__ outb) {
    int node = blockIdx.x * 16 + (threadIdx.x >> 4);
    if (node >= NODES) return;
    int hl = threadIdx.x & 15;
    const uint2* tbu = (const uint2*)tb;
    const float4 bb = ((const float4*)b3)[hl];
    int j = g_rowptr[node];
    int end = g_rowptr[node + 1];
    float a0 = 0.f, a1 = 0.f, a2 = 0.f, a3 = 0.f;
    for (; j + 3 < end; j += 4) {
        int2 e0 = g_csr[j], e1 = g_csr[j + 1], e2 = g_csr[j + 2], e3 = g_csr[j + 3];
        uint2 v0 = tbu[(long)e0.x * 16 + hl];
        uint2 v1 = tbu[(long)e1.x * 16 + hl];
        uint2 v2 = tbu[(long)e2.x * 16 + hl];
        uint2 v3 = tbu[(long)e3.x * 16 + hl];
        ACC_EDGE(e0, v0) ACC_EDGE(e1, v1) ACC_EDGE(e2, v2) ACC_EDGE(e3, v3)
    }
    for (; j < end; j++) {
        int2 e0 = g_csr[j];
        uint2 v0 = tbu[(long)e0.x * 16 + hl];
        ACC_EDGE(e0, v0)
    }
    float nd = g_nd[node];
    float r0 = fmaxf(fmaf(a0, nd, bb.x), 0.0f);
    float r1 = fmaxf(fmaf(a1, nd, bb.y), 0.0f);
    float r2 = fmaxf(fmaf(a2, nd, bb.z), 0.0f);
    float r3 = fmaxf(fmaf(a3, nd, bb.w), 0.0f);
    __nv_bfloat162 p0 = __floats2bfloat162_rn(r0, r1);
    __nv_bfloat162 p1 = __floats2bfloat162_rn(r2, r3);
    uint2 pk;
    pk.x = *(unsigned*)&p0;
    pk.y = *(unsigned*)&p1;
    *(uint2*)&outb[(long)node * (HF / 2) + 2 * hl] = pk;
}

// ---------------- pool (mean per graph) + MLP head + sigmoid ------------------
__device__ __forceinline__ int lower_bound_dev(const int* __restrict__ a, int n, int key) {
    int lo = 0, hi = n;
    while (lo < hi) {
        int mid = (lo + hi) >> 1;
        if (a[mid] < key) lo = mid + 1; else hi = mid;
    }
    return lo;
}

__global__ void pool_mlp_kernel(const __nv_bfloat162* __restrict__ aggb,
                                const int* __restrict__ gid,
                                const float* __restrict__ Dw1, const float* __restrict__ Db1,
                                const float* __restrict__ Dw2, const float* __restrict__ Db2,
                                const float* __restrict__ Dw3, const float* __restrict__ Db3,
                                float* __restrict__ out) {
    int g = blockIdx.x;
    int t = threadIdx.x;  // 32 threads: t covers bf16x2 slot (2 features)
    int start = lower_bound_dev(gid, NODES, g);
    int end = lower_bound_dev(gid, NODES, g + 1);

    float s0 = 0.0f, s1 = 0.0f;
    for (int n = start; n < end; n++) {
        float2 v = __bfloat1622float2(aggb[(long)n * (HF / 2) + t]);
        s0 += v.x;
        s1 += v.y;
    }
    float cnt = fmaxf((float)(end - start), 1.0f);

    __shared__ float pooled[64];
    __shared__ float h1[16];
    __shared__ float h2[8];
    pooled[2 * t] = s0 / cnt;
    pooled[2 * t + 1] = s1 / cnt;
    __syncthreads();

    if (t < 16) {
        float s = Db1[t];
#pragma unroll
        for (int k = 0; k < 64; k++) s = fmaf(pooled[k], Dw1[k * 16 + t], s);
        h1[t] = fmaxf(s, 0.0f);
    }
    __syncthreads();
    if (t < 8) {
        float s = Db2[t];
#pragma unroll
        for (int k = 0; k < 16; k++) s = fmaf(h1[k], Dw2[k * 8 + t], s);
        h2[t] = fmaxf(s, 0.0f);
    }
    __syncthreads();
    if (t == 0) {
        float s = Db3[0];
#pragma unroll
        for (int k = 0; k < 8; k++) s = fmaf(h2[k], Dw3[k], s);
        out[g] = 1.0f / (1.0f + expf(-s));
    }
}

// ---------------- launch ------------------------------------------------------
extern "C" void kernel_launch(void* const* d_in, const int* in_sizes, int n_in,
                              void* d_out, int out_size) {
    const float* x   = (const float*)d_in[0];
    const int*   src = (const int*)d_in[1];
    const int*   dst = (const int*)d_in[2];
    const float* ew  = (const float*)d_in[3];
    const int*   gid = (const int*)d_in[4];
    const float* W1  = (const float*)d_in[5];
    const float* b1  = (const float*)d_in[6];
    const float* W2  = (const float*)d_in[7];
    const float* b2  = (const float*)d_in[8];
    const float* W3  = (const float*)d_in[9];
    const float* b3  = (const float*)d_in[10];
    const float* Dw1 = (const float*)d_in[11];
    const float* Db1 = (const float*)d_in[12];
    const float* Dw2 = (const float*)d_in[13];
    const float* Db2 = (const float*)d_in[14];
    const float* Dw3 = (const float*)d_in[15];
    const float* Db3 = (const float*)d_in[16];
    float* out = (float*)d_out;

    __nv_bfloat162* tb_ptr;  cudaGetSymbolAddress((void**)&tb_ptr, g_tb);
    __nv_bfloat162* agg_ptr; cudaGetSymbolAddress((void**)&agg_ptr, g_aggb);

    const int NB = (NODES + 255) / 256;
    const int EB = (EDGES + 255) / 256;
    const int GB = (NODES + 63) / 64;    // 64-row tiles
    const int A3B = (NODES + 15) / 16;   // agg3 blocks (16 nodes each)

    // One-time setup: side stream + events + gemm1 dynamic smem opt-in.
    static cudaStream_t s2 = nullptr;
    static cudaEvent_t evA = nullptr, evB = nullptr;
    static bool inited = false;
    if (!inited) {
        cudaFuncSetAttribute(gemm1_kernel, cudaFuncAttributeMaxDynamicSharedMemorySize,
                             GEMM1_SMEM);
        if (cudaStreamCreateWithFlags(&s2, cudaStreamNonBlocking) != cudaSuccess) s2 = nullptr;
        if (s2) {
            if (cudaEventCreateWithFlags(&evA, cudaEventDisableTiming) != cudaSuccess ||
                cudaEventCreateWithFlags(&evB, cudaEventDisableTiming) != cudaSuccess) {
                s2 = nullptr;
            }
        }
        inited = true;
    }

    // 1-2: degree histogram (common dependency)
    zero_counts_kernel<<<NB, 256>>>();
    degree_kernel<<<EB, 256>>>(src, dst);

    if (s2) {
        // fork: CSR build on s2, norms+gemm1 on main — independent given degrees
        cudaEventRecord(evA, 0);
        cudaStreamWaitEvent(s2, evA, 0);

        norm_kernel<<<NB, 256>>>();
        gemm1_kernel<<<GB, 256, GEMM1_SMEM>>>(x, W1, tb_ptr);

        scan1_kernel<<<NBLK, SCAN_BLK, 0, s2>>>();
        scan2_kernel<<<1, 512, 0, s2>>>();
        scan3_kernel<<<NBLK, SCAN_BLK, 0, s2>>>();
        csr_fill_kernel<<<EB, 256, 0, s2>>>(src, dst, ew);
        cudaEventRecord(evB, s2);
        cudaStreamWaitEvent(0, evB, 0);
    } else {
        // sequential fallback
        norm_kernel<<<NB, 256>>>();
        gemm1_kernel<<<GB, 256, GEMM1_SMEM>>>(x, W1, tb_ptr);
        scan1_kernel<<<NBLK, SCAN_BLK>>>();
        scan2_kernel<<<1, 512>>>();
        scan3_kernel<<<NBLK, SCAN_BLK>>>();
        csr_fill_kernel<<<EB, 256>>>(src, dst, ew);
    }

    // fused agg+transform+GEMM for layers 2 and 3
    fused_layer_kernel<<<GB, 256>>>(tb_ptr, W2, b1, tb_ptr);
    fused_layer_kernel<<<GB, 256>>>(tb_ptr, W3, b2, tb_ptr);

    // layer-3 aggregation + activation (bf16 out)
    agg3_kernel<<<A3B, 256>>>(tb_ptr, b3, agg_ptr);

    // pool + MLP + sigmoid
    pool_mlp_kernel<<<GRAPHS, 32>>>(agg_ptr, gid, Dw1, Db1, Dw2, Db2, Dw3, Db3, out);
}

// round 17
// speedup vs baseline: 1.5002x; 1.0795x over previous
#include <cuda_runtime.h>
#include <cuda_bf16.h>
#include <math.h>

// Problem constants (fixed by the dataset)
#define NODES 100000
#define EDGES 1600000
#define GRAPHS 256
#define INF 128
#define HF 64
#define SCAN_BLK 256
#define NBLK ((NODES + SCAN_BLK - 1) / SCAN_BLK)   // 391

// ---------------- scratch (static device globals; no allocation) -------------
__device__ int   g_cnt_out[NODES];
__device__ int   g_cnt_in[NODES];
__device__ int   g_rowptr[NODES + 1];
__device__ int   g_cursor[NODES];
__device__ int2  g_csr[EDGES];                     // {src, w-bits}
__device__ int   g_blockSums[NBLK];
__device__ int   g_blockOff[NBLK];
__device__ __nv_bfloat162 g_tb[NODES * (HF / 2)];  // per-layer GEMM output (bf16x2)
__device__ float g_pool[GRAPHS * HF];              // per-graph feature sums (fp32)

// ---------------- init: zero degree counters + pool sums ----------------------
__global__ void zero_counts_kernel() {
    int i = blockIdx.x * blockDim.x + threadIdx.x;
    if (i < NODES) { g_cnt_out[i] = 0; g_cnt_in[i] = 0; }
    if (i < GRAPHS * HF) g_pool[i] = 0.0f;
}

// ---------------- degree histogram -------------------------------------------
__global__ void degree_kernel(const int* __restrict__ src, const int* __restrict__ dst) {
    int e = blockIdx.x * blockDim.x + threadIdx.x;
    if (e < EDGES) {
        atomicAdd(&g_cnt_out[src[e]], 1);
        atomicAdd(&g_cnt_in[dst[e]], 1);
    }
}

// ---------------- 3-phase parallel scan of deg_in -----------------------------
__global__ void scan1_kernel() {
    int i = blockIdx.x * SCAN_BLK + threadIdx.x;
    int c = (i < NODES) ? g_cnt_in[i] : 0;
#pragma unroll
    for (int d = 16; d; d >>= 1) c += __shfl_down_sync(0xffffffffu, c, d);
    __shared__ int w[SCAN_BLK / 32];
    if ((threadIdx.x & 31) == 0) w[threadIdx.x >> 5] = c;
    __syncthreads();
    if (threadIdx.x < SCAN_BLK / 32) {
        int s = w[threadIdx.x];
#pragma unroll
        for (int d = SCAN_BLK / 64; d; d >>= 1) s += __shfl_down_sync(0xffu, s, d);
        if (threadIdx.x == 0) g_blockSums[blockIdx.x] = s;
    }
}

__global__ void scan2_kernel() {
    __shared__ int ss[512];
    int t = threadIdx.x;
    int v = (t < NBLK) ? g_blockSums[t] : 0;
    ss[t] = v;
    __syncthreads();
    for (int d = 1; d < 512; d <<= 1) {
        int o = (t >= d) ? ss[t - d] : 0;
        __syncthreads();
        ss[t] += o;
        __syncthreads();
    }
    if (t < NBLK) g_blockOff[t] = ss[t] - v;  // exclusive
}

__global__ void scan3_kernel() {
    int i = blockIdx.x * SCAN_BLK + threadIdx.x;
    int c = (i < NODES) ? g_cnt_in[i] : 0;
    int lane = threadIdx.x & 31, wid = threadIdx.x >> 5;
    int v = c;
#pragma unroll
    for (int d = 1; d < 32; d <<= 1) {
        int n = __shfl_up_sync(0xffffffffu, v, d);
        if (lane >= d) v += n;
    }
    __shared__ int wsum[SCAN_BLK / 32];
    if (lane == 31) wsum[wid] = v;
    __syncthreads();
    if (threadIdx.x < SCAN_BLK / 32) {
        int s = wsum[threadIdx.x];
#pragma unroll
        for (int d = 1; d < SCAN_BLK / 32; d <<= 1) {
            int n = __shfl_up_sync(0xffu, s, d);
            if ((int)threadIdx.x >= d) s += n;
        }
        wsum[threadIdx.x] = s;
    }
    __syncthreads();
    int excl = v - c + (wid > 0 ? wsum[wid - 1] : 0) + g_blockOff[blockIdx.x];
    if (i < NODES) {
        g_rowptr[i] = excl;
        g_cursor[i] = excl;
    }
    if (blockIdx.x == 0 && threadIdx.x == 0) g_rowptr[NODES] = EDGES;
}

// ---------------- CSR fill (by dst), packed int2 ------------------------------
__global__ void csr_fill_kernel(const int* __restrict__ src, const int* __restrict__ dst,
                                const float* __restrict__ ew) {
    int e = blockIdx.x * blockDim.x + threadIdx.x;
    if (e < EDGES) {
        int d = dst[e];
        int p = atomicAdd(&g_cursor[d], 1);
        g_csr[p] = make_int2(src[e], __float_as_int(ew[e]));
    }
}

// ---------------- layer-1 tf32 GEMM: tb = bf16( ns * (x @ W1) ) ---------------
#define ASTRIDE 132  // fp32 per A row: a-frag bank = 4*qr+qc (conflict-free)
#define BSTRIDE 72   // fp32 per W row: 72%32=8 -> b-frag bank = 8*qc+qr (conflict-free)
#define GEMM1_SMEM ((64 * ASTRIDE + 128 * BSTRIDE) * 4)  // 70656 B

__device__ __forceinline__ void mma_tf32(float* d, const unsigned* a, const unsigned* b) {
    asm volatile(
        "mma.sync.aligned.m16n8k8.row.col.f32.tf32.tf32.f32 "
        "{%0,%1,%2,%3}, {%4,%5,%6,%7}, {%8,%9}, {%0,%1,%2,%3};\n"
        : "+f"(d[0]), "+f"(d[1]), "+f"(d[2]), "+f"(d[3])
        : "r"(a[0]), "r"(a[1]), "r"(a[2]), "r"(a[3]), "r"(b[0]), "r"(b[1]));
}

__device__ __forceinline__ void cp_async16(void* smem_dst, const void* gmem_src, int srcBytes) {
    unsigned saddr = (unsigned)__cvta_generic_to_shared(smem_dst);
    asm volatile("cp.async.cg.shared.global [%0], [%1], 16, %2;"
                 :: "r"(saddr), "l"(gmem_src), "r"(srcBytes));
}

__global__ void __launch_bounds__(256) gemm1_kernel(const float* __restrict__ A,
                                                    const float* __restrict__ W,
                                                    __nv_bfloat162* __restrict__ outb) {
    extern __shared__ float smem_[];
    float* sA = smem_;                     // [64][ASTRIDE] raw fp32 bits
    float* sB = smem_ + 64 * ASTRIDE;      // [128][BSTRIDE] W as-is [k][n]

    const int tid = threadIdx.x;           // 0..255
    const int wid = tid >> 5;
    const int lane = tid & 31;
    const int qr = lane >> 2;
    const int qc = lane & 3;
    const int warp_m = wid & 3;            // 4 m-warps, 16 rows each
    const int warp_n = wid >> 2;           // 2 n-warps, 32 cols each
    const int row0 = blockIdx.x * 64;

    // ---- stage A tile: 64 rows x 128 floats = 2048 x 16B, 8 per thread ----
#pragma unroll
    for (int it = 0; it < 8; it++) {
        int idx = it * 256 + tid;
        int row = idx >> 5;                // 32 chunks per row
        int c = idx & 31;
        int grow = row0 + row;
        int ok = (grow < NODES) ? 16 : 0;
        int srow = (grow < NODES) ? grow : (NODES - 1);
        cp_async16(&sA[row * ASTRIDE + c * 4], &A[(long)srow * INF + c * 4], ok);
    }
    // ---- stage W: 128 rows x 64 floats = 2048 x 16B, 8 per thread ----
#pragma unroll
    for (int it = 0; it < 8; it++) {
        int idx = it * 256 + tid;
        int row = idx >> 4;                // 16 chunks per row
        int c = idx & 15;
        cp_async16(&sB[row * BSTRIDE + c * 4], &W[(long)row * HF + c * 4], 16);
    }
    asm volatile("cp.async.commit_group;");
    asm volatile("cp.async.wait_group 0;");
    __syncthreads();

    const unsigned* sAu = (const unsigned*)sA;
    const unsigned* sBu = (const unsigned*)sB;

    float acc[4][4];
#pragma unroll
    for (int ni = 0; ni < 4; ni++)
#pragma unroll
        for (int j = 0; j < 4; j++) acc[ni][j] = 0.0f;

#pragma unroll
    for (int kk8 = 0; kk8 < 16; kk8++) {
        const int kk = kk8 * 8;
        unsigned a[4], b[4][2];
        int r = warp_m * 16 + qr;
        a[0] = sAu[r * ASTRIDE + kk + qc];
        a[1] = sAu[(r + 8) * ASTRIDE + kk + qc];
        a[2] = sAu[r * ASTRIDE + kk + qc + 4];
        a[3] = sAu[(r + 8) * ASTRIDE + kk + qc + 4];
#pragma unroll
        for (int ni = 0; ni < 4; ni++) {
            int n = warp_n * 32 + ni * 8 + qr;
            b[ni][0] = sBu[(kk + qc) * BSTRIDE + n];
            b[ni][1] = sBu[(kk + qc + 4) * BSTRIDE + n];
        }
#pragma unroll
        for (int ni = 0; ni < 4; ni++)
            mma_tf32(acc[ni], a, b[ni]);
    }

    // ---- epilogue: row-scale by ns (inline rsqrt of out-degree), pack bf16x2 --
    int r0 = row0 + warp_m * 16 + qr;
    int r1 = r0 + 8;
    float ns0 = (r0 < NODES) ? rsqrtf(fmaxf((float)g_cnt_out[r0], 1.0f)) : 0.0f;
    float ns1 = (r1 < NODES) ? rsqrtf(fmaxf((float)g_cnt_out[r1], 1.0f)) : 0.0f;
#pragma unroll
    for (int ni = 0; ni < 4; ni++) {
        int col2 = (warp_n * 32 + ni * 8 + qc * 2) >> 1;
        if (r0 < NODES)
            outb[(long)r0 * (HF / 2) + col2] =
                __floats2bfloat162_rn(acc[ni][0] * ns0, acc[ni][1] * ns0);
        if (r1 < NODES)
            outb[(long)r1 * (HF / 2) + col2] =
                __floats2bfloat162_rn(acc[ni][2] * ns1, acc[ni][3] * ns1);
    }
}

// ---------------- fused layer: agg(tb_in) -> transform -> bf16 GEMM -> tb_out -
// Phase A: half-warp per node, 4-edge unroll, dynamic row assignment.
// Phase B: 64x64 GEMM via mma.m16n8k16 bf16.
#define BPAD 72  // bf16 elems per row; 144B stride -> conflict-free frag loads

__device__ __forceinline__ void mma_bf16(float* d, const unsigned* a, const unsigned* b) {
    asm volatile(
        "mma.sync.aligned.m16n8k16.row.col.f32.bf16.bf16.f32 "
        "{%0,%1,%2,%3}, {%4,%5,%6,%7}, {%8,%9}, {%0,%1,%2,%3};\n"
        : "+f"(d[0]), "+f"(d[1]), "+f"(d[2]), "+f"(d[3])
        : "r"(a[0]), "r"(a[1]), "r"(a[2]), "r"(a[3]), "r"(b[0]), "r"(b[1]));
}

#define ACC_EDGE(e, v)                                                        \
    {                                                                         \
        float w = __int_as_float((e).y);                                      \
        float2 lo = __bfloat1622float2(*(__nv_bfloat162*)&(v).x);             \
        float2 hi = __bfloat1622float2(*(__nv_bfloat162*)&(v).y);             \
        a0 = fmaf(lo.x, w, a0); a1 = fmaf(lo.y, w, a1);                       \
        a2 = fmaf(hi.x, w, a2); a3 = fmaf(hi.y, w, a3);                       \
    }

__global__ void fused_layer_kernel(const __nv_bfloat162* __restrict__ tb_in,
                                   const float* __restrict__ W,
                                   const float* __restrict__ bprev,
                                   __nv_bfloat162* __restrict__ tb_out) {
    __shared__ __nv_bfloat16 sA[64 * BPAD];  // [row][k]
    __shared__ __nv_bfloat16 sW[64 * BPAD];  // [n][k] (W transposed)
    __shared__ int s_next;                   // dynamic row cursor (0..63)

    const int tid = threadIdx.x;     // 0..255
    const int wid = tid >> 5;        // 0..7
    const int lane = tid & 31;
    const int row0 = blockIdx.x * 64;
    const uint2* tbu = (const uint2*)tb_in;  // [node][16] x 8B (4 bf16 each)

    if (tid == 0) s_next = 0;

    // load W transposed -> sW[n][k]
#pragma unroll
    for (int it = 0; it < 16; it++) {
        int idx = it * 256 + tid;    // 4096
        int k = idx >> 6;
        int n = idx & 63;
        sW[n * BPAD + k] = __float2bfloat16(W[k * HF + n]);
    }
    __syncthreads();                 // s_next visible before pops

    // Phase A: half-warp per node, rows popped dynamically
    const int hl = lane & 15;        // 0..15 -> features 4*hl..4*hl+3
    const int hsrc = lane & 16;      // shuffle source lane (0 or 16)
    const unsigned hmask = (lane < 16) ? 0x0000FFFFu : 0xFFFF0000u;
    const float4 bb = ((const float4*)bprev)[hl];
    while (true) {
        int lrow = 0;
        if (hl == 0) lrow = atomicAdd(&s_next, 1);
        lrow = __shfl_sync(hmask, lrow, hsrc);
        if (lrow >= 64) break;
        int row = row0 + lrow;
        float a0 = 0.f, a1 = 0.f, a2 = 0.f, a3 = 0.f;
        int j = 0, end = 0;
        if (row < NODES) { j = g_rowptr[row]; end = g_rowptr[row + 1]; }
        for (; j + 3 < end; j += 4) {
            int2 e0 = g_csr[j], e1 = g_csr[j + 1], e2 = g_csr[j + 2], e3 = g_csr[j + 3];
            uint2 v0 = tbu[(long)e0.x * 16 + hl];
            uint2 v1 = tbu[(long)e1.x * 16 + hl];
            uint2 v2 = tbu[(long)e2.x * 16 + hl];
            uint2 v3 = tbu[(long)e3.x * 16 + hl];
            ACC_EDGE(e0, v0) ACC_EDGE(e1, v1) ACC_EDGE(e2, v2) ACC_EDGE(e3, v3)
        }
        for (; j < end; j++) {
            int2 e0 = g_csr[j];
            uint2 v0 = tbu[(long)e0.x * 16 + hl];
            ACC_EDGE(e0, v0)
        }
        if (row < NODES) {
            float nd = rsqrtf(fmaxf((float)g_cnt_in[row], 1.0f));
            float ns = rsqrtf(fmaxf((float)g_cnt_out[row], 1.0f));
            a0 = fmaxf(fmaf(a0, nd, bb.x), 0.0f) * ns;
            a1 = fmaxf(fmaf(a1, nd, bb.y), 0.0f) * ns;
            a2 = fmaxf(fmaf(a2, nd, bb.z), 0.0f) * ns;
            a3 = fmaxf(fmaf(a3, nd, bb.w), 0.0f) * ns;
        }
        __nv_bfloat162 p0 = __floats2bfloat162_rn(a0, a1);
        __nv_bfloat162 p1 = __floats2bfloat162_rn(a2, a3);
        uint2 pk;
        pk.x = *(unsigned*)&p0;
        pk.y = *(unsigned*)&p1;
        *(uint2*)&sA[lrow * BPAD + 4 * hl] = pk;
    }
    __syncthreads();

    // Phase B: GEMM sA @ sW^T
    const int warp_m = wid & 3;
    const int warp_n = wid >> 2;
    const int qr = lane >> 2;
    const int qc = lane & 3;

    float acc[4][4];
#pragma unroll
    for (int ni = 0; ni < 4; ni++)
#pragma unroll
        for (int j = 0; j < 4; j++) acc[ni][j] = 0.0f;

#pragma unroll
    for (int ks = 0; ks < 4; ks++) {
        const int kk = ks * 16;
        unsigned a[4], b[4][2];
        int ra = warp_m * 16 + qr;
        a[0] = *(const unsigned*)&sA[ra * BPAD + kk + 2 * qc];
        a[1] = *(const unsigned*)&sA[(ra + 8) * BPAD + kk + 2 * qc];
        a[2] = *(const unsigned*)&sA[ra * BPAD + kk + 2 * qc + 8];
        a[3] = *(const unsigned*)&sA[(ra + 8) * BPAD + kk + 2 * qc + 8];
#pragma unroll
        for (int ni = 0; ni < 4; ni++) {
            int n = warp_n * 32 + ni * 8 + qr;
            b[ni][0] = *(const unsigned*)&sW[n * BPAD + kk + 2 * qc];
            b[ni][1] = *(const unsigned*)&sW[n * BPAD + kk + 2 * qc + 8];
        }
#pragma unroll
        for (int ni = 0; ni < 4; ni++)
            mma_bf16(acc[ni], a, b[ni]);
    }

    // epilogue
    int r0 = row0 + warp_m * 16 + qr;
    int r1 = r0 + 8;
#pragma unroll
    for (int ni = 0; ni < 4; ni++) {
        int col2 = (warp_n * 32 + ni * 8 + qc * 2) >> 1;
        if (r0 < NODES)
            tb_out[(long)r0 * (HF / 2) + col2] = __floats2bfloat162_rn(acc[ni][0], acc[ni][1]);
        if (r1 < NODES)
            tb_out[(long)r1 * (HF / 2) + col2] = __floats2bfloat162_rn(acc[ni][2], acc[ni][3]);
    }
}

// ---------------- layer-3 agg + activate + per-graph pooling ------------------
// half-warp per node, 4-edge unroll; block covers 16 consecutive nodes (gid
// sorted). Segment-reduce activated vectors per gid in smem, then one
// atomicAdd per (gid, feature) per segment into g_pool.
__global__ void agg3_pool_kernel(const __nv_bfloat162* __restrict__ tb,
                                 const float* __restrict__ b3,
                                 const int* __restrict__ gid) {
    __shared__ float s_act[16][HF + 4];
    __shared__ int s_gid[16];

    int n16 = threadIdx.x >> 4;          // 0..15 (node slot)
    int node = blockIdx.x * 16 + n16;
    int hl = threadIdx.x & 15;
    const uint2* tbu = (const uint2*)tb;
    const float4 bb = ((const float4*)b3)[hl];

    float a0 = 0.f, a1 = 0.f, a2 = 0.f, a3 = 0.f;
    if (node < NODES) {
        int j = g_rowptr[node];
        int end = g_rowptr[node + 1];
        for (; j + 3 < end; j += 4) {
            int2 e0 = g_csr[j], e1 = g_csr[j + 1], e2 = g_csr[j + 2], e3 = g_csr[j + 3];
            uint2 v0 = tbu[(long)e0.x * 16 + hl];
            uint2 v1 = tbu[(long)e1.x * 16 + hl];
            uint2 v2 = tbu[(long)e2.x * 16 + hl];
            uint2 v3 = tbu[(long)e3.x * 16 + hl];
            ACC_EDGE(e0, v0) ACC_EDGE(e1, v1) ACC_EDGE(e2, v2) ACC_EDGE(e3, v3)
        }
        for (; j < end; j++) {
            int2 e0 = g_csr[j];
            uint2 v0 = tbu[(long)e0.x * 16 + hl];
            ACC_EDGE(e0, v0)
        }
        float nd = rsqrtf(fmaxf((float)g_cnt_in[node], 1.0f));
        a0 = fmaxf(fmaf(a0, nd, bb.x), 0.0f);
        a1 = fmaxf(fmaf(a1, nd, bb.y), 0.0f);
        a2 = fmaxf(fmaf(a2, nd, bb.z), 0.0f);
        a3 = fmaxf(fmaf(a3, nd, bb.w), 0.0f);
        if (hl == 0) s_gid[n16] = gid[node];
    } else {
        a0 = a1 = a2 = a3 = 0.f;
        if (hl == 0) s_gid[n16] = -1;
    }
    float4* dst = (float4*)&s_act[n16][4 * hl];
    *dst = make_float4(a0, a1, a2, a3);
    __syncthreads();

    // segment-reduce over the 16 nodes; threads 0..63 each own one feature
    if (threadIdx.x < HF) {
        int f = threadIdx.x;
        int cur = s_gid[0];
        float sum = 0.0f;
#pragma unroll
        for (int i = 0; i < 16; i++) {
            int g = s_gid[i];
            if (g != cur) {
                if (cur >= 0) atomicAdd(&g_pool[cur * HF + f], sum);
                sum = 0.0f;
                cur = g;
            }
            sum += s_act[i][f];
        }
        if (cur >= 0) atomicAdd(&g_pool[cur * HF + f], sum);
    }
}

// ---------------- final: mean + MLP head + sigmoid ----------------------------
__device__ __forceinline__ int lower_bound_dev(const int* __restrict__ a, int n, int key) {
    int lo = 0, hi = n;
    while (lo < hi) {
        int mid = (lo + hi) >> 1;
        if (a[mid] < key) lo = mid + 1; else hi = mid;
    }
    return lo;
}

__global__ void mlp_kernel(const int* __restrict__ gid,
                           const float* __restrict__ Dw1, const float* __restrict__ Db1,
                           const float* __restrict__ Dw2, const float* __restrict__ Db2,
                           const float* __restrict__ Dw3, const float* __restrict__ Db3,
                           float* __restrict__ out) {
    int g = blockIdx.x;
    int t = threadIdx.x;  // 64 threads
    int start = lower_bound_dev(gid, NODES, g);
    int end = lower_bound_dev(gid, NODES, g + 1);
    float cnt = fmaxf((float)(end - start), 1.0f);

    __shared__ float pooled[64];
    __shared__ float h1[16];
    __shared__ float h2[8];
    pooled[t] = g_pool[g * HF + t] / cnt;
    __syncthreads();

    if (t < 16) {
        float s = Db1[t];
#pragma unroll
        for (int k = 0; k < 64; k++) s = fmaf(pooled[k], Dw1[k * 16 + t], s);
        h1[t] = fmaxf(s, 0.0f);
    }
    __syncthreads();
    if (t < 8) {
        float s = Db2[t];
#pragma unroll
        for (int k = 0; k < 16; k++) s = fmaf(h1[k], Dw2[k * 8 + t], s);
        h2[t] = fmaxf(s, 0.0f);
    }
    __syncthreads();
    if (t == 0) {
        float s = Db3[0];
#pragma unroll
        for (int k = 0; k < 8; k++) s = fmaf(h2[k], Dw3[k], s);
        out[g] = 1.0f / (1.0f + expf(-s));
    }
}

// ---------------- launch ------------------------------------------------------
extern "C" void kernel_launch(void* const* d_in, const int* in_sizes, int n_in,
                              void* d_out, int out_size) {
    const float* x   = (const float*)d_in[0];
    const int*   src = (const int*)d_in[1];
    const int*   dst = (const int*)d_in[2];
    const float* ew  = (const float*)d_in[3];
    const int*   gid = (const int*)d_in[4];
    const float* W1  = (const float*)d_in[5];
    const float* b1  = (const float*)d_in[6];
    const float* W2  = (const float*)d_in[7];
    const float* b2  = (const float*)d_in[8];
    const float* W3  = (const float*)d_in[9];
    const float* b3  = (const float*)d_in[10];
    const float* Dw1 = (const float*)d_in[11];
    const float* Db1 = (const float*)d_in[12];
    const float* Dw2 = (const float*)d_in[13];
    const float* Db2 = (const float*)d_in[14];
    const float* Dw3 = (const float*)d_in[15];
    const float* Db3 = (const float*)d_in[16];
    float* out = (float*)d_out;

    __nv_bfloat162* tb_ptr; cudaGetSymbolAddress((void**)&tb_ptr, g_tb);

    const int NB = (NODES + 255) / 256;
    const int EB = (EDGES + 255) / 256;
    const int GB = (NODES + 63) / 64;    // 64-row tiles
    const int A3B = (NODES + 15) / 16;   // agg3 blocks (16 nodes each)

    // One-time setup: side stream + events + gemm1 dynamic smem opt-in.
    static cudaStream_t s2 = nullptr;
    static cudaEvent_t evA = nullptr, evB = nullptr;
    static bool inited = false;
    if (!inited) {
        cudaFuncSetAttribute(gemm1_kernel, cudaFuncAttributeMaxDynamicSharedMemorySize,
                             GEMM1_SMEM);
        if (cudaStreamCreateWithFlags(&s2, cudaStreamNonBlocking) != cudaSuccess) s2 = nullptr;
        if (s2) {
            if (cudaEventCreateWithFlags(&evA, cudaEventDisableTiming) != cudaSuccess ||
                cudaEventCreateWithFlags(&evB, cudaEventDisableTiming) != cudaSuccess) {
                s2 = nullptr;
            }
        }
        inited = true;
    }

    // 1-2: degree histogram (common dependency); zero also clears g_pool
    zero_counts_kernel<<<NB, 256>>>();
    degree_kernel<<<EB, 256>>>(src, dst);

    if (s2) {
        // fork: CSR build on s2, gemm1 on main — independent given degrees
        cudaEventRecord(evA, 0);
        cudaStreamWaitEvent(s2, evA, 0);

        gemm1_kernel<<<GB, 256, GEMM1_SMEM>>>(x, W1, tb_ptr);

        scan1_kernel<<<NBLK, SCAN_BLK, 0, s2>>>();
        scan2_kernel<<<1, 512, 0, s2>>>();
        scan3_kernel<<<NBLK, SCAN_BLK, 0, s2>>>();
        csr_fill_kernel<<<EB, 256, 0, s2>>>(src, dst, ew);
        cudaEventRecord(evB, s2);
        cudaStreamWaitEvent(0, evB, 0);
    } else {
        // sequential fallback
        gemm1_kernel<<<GB, 256, GEMM1_SMEM>>>(x, W1, tb_ptr);
        scan1_kernel<<<NBLK, SCAN_BLK>>>();
        scan2_kernel<<<1, 512>>>();
        scan3_kernel<<<NBLK, SCAN_BLK>>>();
        csr_fill_kernel<<<EB, 256>>>(src, dst, ew);
    }

    // fused agg+transform+GEMM for layers 2 and 3
    fused_layer_kernel<<<GB, 256>>>(tb_ptr, W2, b1, tb_ptr);
    fused_layer_kernel<<<GB, 256>>>(tb_ptr, W3, b2, tb_ptr);

    // layer-3 aggregation + activation + per-graph pooling (fused)
    agg3_pool_kernel<<<A3B, 256>>>(tb_ptr, b3, gid);

    // mean + MLP + sigmoid
    mlp_kernel<<<GRAPHS, 64>>>(gid, Dw1, Db1, Dw2, Db2, Dw3, Db3, out);
}